// round 1
// baseline (speedup 1.0000x reference)
#include <cuda_runtime.h>
#include <math.h>

#define BSZ  64
#define LEN  256
#define DM   512
#define DFF  2048
#define NEXP 992
#define M1   (BSZ * LEN)            // 16384
#define NSPLIT 8
#define ZSCALE 0.044194173824159216f   // 1/sqrt(512)

// ------------------------- scratch (static device globals) -------------------------
static __device__ float g_X2  [(size_t)M1 * DM];
static __device__ float g_XK  [(size_t)M1 * DM];
static __device__ float g_EA0 [(size_t)M1 * DM];
static __device__ float g_EB0 [(size_t)M1 * DM];
static __device__ float g_AE  [(size_t)M1 * DM];
static __device__ float g_BE  [(size_t)M1 * DM];
static __device__ float g_SEL [(size_t)M1 * DM];
static __device__ float g_X1  [(size_t)M1 * DM];
static __device__ float g_Z   [(size_t)BSZ * NEXP * LEN];
static __device__ float g_CA  [(size_t)BSZ * NEXP * DM];
static __device__ float g_CB  [(size_t)BSZ * NEXP * DM];
static __device__ float g_H   [(size_t)M1 * DFF];
static __device__ float g_IAf [BSZ * NEXP];
static __device__ float g_IBf [BSZ * NEXP];
static __device__ float g_PA  [BSZ * NSPLIT * LEN];
static __device__ float g_PB  [BSZ * NSPLIT * LEN];
static __device__ float g_IAb [BSZ * LEN];
static __device__ float g_IBb [BSZ * LEN];

// ------------------------- LayerNorm: one block (128 thr) per row -------------------------
__global__ void ln_kernel(const float* __restrict__ X, const float* __restrict__ G,
                          const float* __restrict__ B, float* __restrict__ O)
{
    __shared__ float sred[4];
    int row = blockIdx.x;
    int t = threadIdx.x;                       // 128 threads, 4 floats each
    const float4 v = reinterpret_cast<const float4*>(X + (size_t)row * DM)[t];
    float s = v.x + v.y + v.z + v.w;
    #pragma unroll
    for (int o = 16; o; o >>= 1) s += __shfl_down_sync(0xffffffffu, s, o);
    if ((t & 31) == 0) sred[t >> 5] = s;
    __syncthreads();
    float mu = (sred[0] + sred[1] + sred[2] + sred[3]) * (1.0f / DM);
    __syncthreads();
    float4 d;
    d.x = v.x - mu; d.y = v.y - mu; d.z = v.z - mu; d.w = v.w - mu;
    float ss = d.x * d.x + d.y * d.y + d.z * d.z + d.w * d.w;
    #pragma unroll
    for (int o = 16; o; o >>= 1) ss += __shfl_down_sync(0xffffffffu, ss, o);
    if ((t & 31) == 0) sred[t >> 5] = ss;
    __syncthreads();
    float var = (sred[0] + sred[1] + sred[2] + sred[3]) * (1.0f / DM);
    float rstd = rsqrtf(var + 1e-5f);
    const float4 g4 = reinterpret_cast<const float4*>(G)[t];
    const float4 b4 = reinterpret_cast<const float4*>(B)[t];
    float4 o4;
    o4.x = d.x * rstd * g4.x + b4.x;
    o4.y = d.y * rstd * g4.y + b4.y;
    o4.z = d.z * rstd * g4.z + b4.z;
    o4.w = d.w * rstd * g4.w + b4.w;
    reinterpret_cast<float4*>(O + (size_t)row * DM)[t] = o4;
}

// ------------------------- generic NN SGEMM (64x64x16, 4x4 micro) -------------------------
// MODE 0: C = acc + bias
// MODE 1: C = sigmoid(acc + bias)
// MODE 2: C = relu(acc + bias)
// MODE 3: C = Dm * sigmoid(acc + bias)        (gated)
// MODE 4: C = Dm + acc + bias                 (residual)
template <int MODE>
__global__ void __launch_bounds__(256) sgemm_nn(
    const float* __restrict__ A, const float* __restrict__ B,
    const float* __restrict__ bias, const float* __restrict__ Dm,
    float* __restrict__ C, int M, int N, int K)
{
    __shared__ float As[16][64];
    __shared__ float Bs[16][64];
    int tid = threadIdx.x;
    int bm = blockIdx.y * 64, bn = blockIdx.x * 64;
    int tx = tid & 15, ty = tid >> 4;
    int arow = tid >> 2, akq = (tid & 3) << 2;
    int bkr = tid >> 4, bcq = (tid & 15) << 2;
    const float* Ap = A + (size_t)(bm + arow) * K + akq;
    const float* Bp = B + (size_t)bkr * N + bn + bcq;
    float acc[4][4] = {};
    for (int k0 = 0; k0 < K; k0 += 16) {
        float4 av = *reinterpret_cast<const float4*>(Ap + k0);
        float4 bv = *reinterpret_cast<const float4*>(Bp + (size_t)k0 * N);
        As[akq + 0][arow] = av.x;
        As[akq + 1][arow] = av.y;
        As[akq + 2][arow] = av.z;
        As[akq + 3][arow] = av.w;
        *reinterpret_cast<float4*>(&Bs[bkr][bcq]) = bv;
        __syncthreads();
        #pragma unroll
        for (int kk = 0; kk < 16; kk++) {
            float4 a4 = *reinterpret_cast<const float4*>(&As[kk][ty << 2]);
            float4 b4 = *reinterpret_cast<const float4*>(&Bs[kk][tx << 2]);
            float ar[4] = {a4.x, a4.y, a4.z, a4.w};
            float br[4] = {b4.x, b4.y, b4.z, b4.w};
            #pragma unroll
            for (int i = 0; i < 4; i++)
                #pragma unroll
                for (int j = 0; j < 4; j++)
                    acc[i][j] += ar[i] * br[j];
        }
        __syncthreads();
    }
    int col0 = bn + (tx << 2);
    float4 bias4 = *reinterpret_cast<const float4*>(bias + col0);
    #pragma unroll
    for (int i = 0; i < 4; i++) {
        int row = bm + (ty << 2) + i;
        size_t off = (size_t)row * N + col0;
        float v[4];
        v[0] = acc[i][0] + bias4.x;
        v[1] = acc[i][1] + bias4.y;
        v[2] = acc[i][2] + bias4.z;
        v[3] = acc[i][3] + bias4.w;
        float4 o4;
        if (MODE == 0) {
            o4 = make_float4(v[0], v[1], v[2], v[3]);
        } else if (MODE == 1) {
            o4 = make_float4(1.f / (1.f + expf(-v[0])), 1.f / (1.f + expf(-v[1])),
                             1.f / (1.f + expf(-v[2])), 1.f / (1.f + expf(-v[3])));
        } else if (MODE == 2) {
            o4 = make_float4(fmaxf(v[0], 0.f), fmaxf(v[1], 0.f),
                             fmaxf(v[2], 0.f), fmaxf(v[3], 0.f));
        } else if (MODE == 3) {
            float4 d4 = *reinterpret_cast<const float4*>(Dm + off);
            o4 = make_float4(d4.x / (1.f + expf(-v[0])), d4.y / (1.f + expf(-v[1])),
                             d4.z / (1.f + expf(-v[2])), d4.w / (1.f + expf(-v[3])));
        } else { // MODE 4
            float4 d4 = *reinterpret_cast<const float4*>(Dm + off);
            o4 = make_float4(d4.x + v[0], d4.y + v[1], d4.z + v[2], d4.w + v[3]);
        }
        *reinterpret_cast<float4*>(C + off) = o4;
    }
}

// ------------------------- z = gather(q_tab) @ x_key^T * scale (batched NT) -------------------------
__global__ void __launch_bounds__(256) zgemm(
    const int* __restrict__ nidx, const float* __restrict__ qtab,
    const float* __restrict__ XK, float* __restrict__ Z)
{
    __shared__ float As[16][64];
    __shared__ float Bs[16][64];
    __shared__ int sidx[64];
    int tid = threadIdx.x;
    int b  = blockIdx.z;
    int bm = blockIdx.y * 64;   // n
    int bl = blockIdx.x * 64;   // l
    if (tid < 64) {
        int n = bm + tid;
        sidx[tid] = (n < NEXP) ? nidx[b * NEXP + n] : 0;
    }
    __syncthreads();
    int tx = tid & 15, ty = tid >> 4;
    int arow = tid >> 2, akq = (tid & 3) << 2;
    const float* Ap = qtab + (size_t)sidx[arow] * DM + akq;
    const float* Bp = XK + (size_t)(b * LEN + bl + arow) * DM + akq;
    float acc[4][4] = {};
    for (int k0 = 0; k0 < DM; k0 += 16) {
        float4 av = *reinterpret_cast<const float4*>(Ap + k0);
        float4 bv = *reinterpret_cast<const float4*>(Bp + k0);
        As[akq + 0][arow] = av.x; As[akq + 1][arow] = av.y;
        As[akq + 2][arow] = av.z; As[akq + 3][arow] = av.w;
        Bs[akq + 0][arow] = bv.x; Bs[akq + 1][arow] = bv.y;
        Bs[akq + 2][arow] = bv.z; Bs[akq + 3][arow] = bv.w;
        __syncthreads();
        #pragma unroll
        for (int kk = 0; kk < 16; kk++) {
            float4 a4 = *reinterpret_cast<const float4*>(&As[kk][ty << 2]);
            float4 b4 = *reinterpret_cast<const float4*>(&Bs[kk][tx << 2]);
            float ar[4] = {a4.x, a4.y, a4.z, a4.w};
            float br[4] = {b4.x, b4.y, b4.z, b4.w};
            #pragma unroll
            for (int i = 0; i < 4; i++)
                #pragma unroll
                for (int j = 0; j < 4; j++)
                    acc[i][j] += ar[i] * br[j];
        }
        __syncthreads();
    }
    float* Zb = Z + (size_t)b * NEXP * LEN;
    #pragma unroll
    for (int i = 0; i < 4; i++) {
        int n = bm + (ty << 2) + i;
        if (n >= NEXP) continue;
        float4 o4 = make_float4(acc[i][0] * ZSCALE, acc[i][1] * ZSCALE,
                                acc[i][2] * ZSCALE, acc[i][3] * ZSCALE);
        *reinterpret_cast<float4*>(Zb + (size_t)n * LEN + bl + (tx << 2)) = o4;
    }
}

// ------------------------- forward row sums: 1/(sum_l masked relu(+-z) + eps) -------------------------
__global__ void fw_sums(const float* __restrict__ Z, const int* __restrict__ mask,
                        float* __restrict__ invA, float* __restrict__ invB)
{
    int gw = (blockIdx.x * blockDim.x + threadIdx.x) >> 5;
    int lane = threadIdx.x & 31;
    if (gw >= BSZ * NEXP) return;
    const float* zr = Z + (size_t)gw * LEN;
    const int* mr = mask + (size_t)gw * LEN;
    float sa = 0.f, sb = 0.f;
    for (int i = lane; i < LEN; i += 32) {
        float z = zr[i];
        if (mr[i]) { sa += fmaxf(z, 0.f); sb += fmaxf(-z, 0.f); }
    }
    #pragma unroll
    for (int o = 16; o; o >>= 1) {
        sa += __shfl_down_sync(0xffffffffu, sa, o);
        sb += __shfl_down_sync(0xffffffffu, sb, o);
    }
    if (!lane) { invA[gw] = 1.f / (sa + 1e-9f); invB[gw] = 1.f / (sb + 1e-9f); }
}

// ------------------------- backward col sums over n (split-K partials + finalize) -------------------------
__global__ void bw_partial(const float* __restrict__ Z, const int* __restrict__ mask,
                           float* __restrict__ psA, float* __restrict__ psB)
{
    int b = blockIdx.x, s = blockIdx.y, l = threadIdx.x;
    float sa = 0.f, sb = 0.f;
    int n0 = s * (NEXP / NSPLIT);
    for (int n = n0; n < n0 + NEXP / NSPLIT; n++) {
        size_t off = ((size_t)b * NEXP + n) * LEN + l;
        float z = Z[off];
        if (mask[off]) { sa += fmaxf(z, 0.f); sb += fmaxf(-z, 0.f); }
    }
    psA[((size_t)b * NSPLIT + s) * LEN + l] = sa;
    psB[((size_t)b * NSPLIT + s) * LEN + l] = sb;
}

__global__ void bw_final(const float* __restrict__ psA, const float* __restrict__ psB,
                         float* __restrict__ invA, float* __restrict__ invB)
{
    int b = blockIdx.x, l = threadIdx.x;
    float sa = 0.f, sb = 0.f;
    for (int s = 0; s < NSPLIT; s++) {
        sa += psA[((size_t)b * NSPLIT + s) * LEN + l];
        sb += psB[((size_t)b * NSPLIT + s) * LEN + l];
    }
    invA[b * LEN + l] = 1.f / (sa + 1e-9f);
    invB[b * LEN + l] = 1.f / (sb + 1e-9f);
}

// ------------------------- forward class GEMM (dual a/b, A on the fly) -------------------------
// CA[b,n,d] = invA[b,n] * sum_l (m ? relu(z) : 0) * AE[b,l,d] + b_tab[idx[b,n],d]
__global__ void __launch_bounds__(256) classfw(
    const float* __restrict__ Z, const int* __restrict__ mask,
    const float* __restrict__ AE, const float* __restrict__ BE,
    const float* __restrict__ invA, const float* __restrict__ invB,
    const int* __restrict__ nidx, const float* __restrict__ btab,
    float* __restrict__ CA, float* __restrict__ CB)
{
    __shared__ float Aa[16][64], Ab[16][64];
    __shared__ float Ba[16][64], Bb[16][64];
    int tid = threadIdx.x;
    int b  = blockIdx.z;
    int bm = blockIdx.y * 64;   // n
    int bn = blockIdx.x * 64;   // d
    int tx = tid & 15, ty = tid >> 4;
    int arow = tid >> 2, akq = (tid & 3) << 2;
    int bkr = tid >> 4, bcq = (tid & 15) << 2;
    int an = bm + arow;
    bool avalid = an < NEXP;
    const float* Zp = Z + ((size_t)b * NEXP + (avalid ? an : 0)) * LEN + akq;
    const int*  Mp = mask + ((size_t)b * NEXP + (avalid ? an : 0)) * LEN + akq;
    const float* AEp = AE + ((size_t)b * LEN + bkr) * DM + bn + bcq;
    const float* BEp = BE + ((size_t)b * LEN + bkr) * DM + bn + bcq;
    float acca[4][4] = {}, accb[4][4] = {};
    for (int k0 = 0; k0 < LEN; k0 += 16) {
        float4 zv = avalid ? *reinterpret_cast<const float4*>(Zp + k0) : make_float4(0, 0, 0, 0);
        int4  mv = avalid ? *reinterpret_cast<const int4*>(Mp + k0) : make_int4(0, 0, 0, 0);
        Aa[akq + 0][arow] = mv.x ? fmaxf(zv.x, 0.f) : 0.f;
        Ab[akq + 0][arow] = mv.x ? fmaxf(-zv.x, 0.f) : 0.f;
        Aa[akq + 1][arow] = mv.y ? fmaxf(zv.y, 0.f) : 0.f;
        Ab[akq + 1][arow] = mv.y ? fmaxf(-zv.y, 0.f) : 0.f;
        Aa[akq + 2][arow] = mv.z ? fmaxf(zv.z, 0.f) : 0.f;
        Ab[akq + 2][arow] = mv.z ? fmaxf(-zv.z, 0.f) : 0.f;
        Aa[akq + 3][arow] = mv.w ? fmaxf(zv.w, 0.f) : 0.f;
        Ab[akq + 3][arow] = mv.w ? fmaxf(-zv.w, 0.f) : 0.f;
        *reinterpret_cast<float4*>(&Ba[bkr][bcq]) = *reinterpret_cast<const float4*>(AEp + (size_t)k0 * DM);
        *reinterpret_cast<float4*>(&Bb[bkr][bcq]) = *reinterpret_cast<const float4*>(BEp + (size_t)k0 * DM);
        __syncthreads();
        #pragma unroll
        for (int kk = 0; kk < 16; kk++) {
            float4 a4  = *reinterpret_cast<const float4*>(&Aa[kk][ty << 2]);
            float4 ab4 = *reinterpret_cast<const float4*>(&Ab[kk][ty << 2]);
            float4 c4  = *reinterpret_cast<const float4*>(&Ba[kk][tx << 2]);
            float4 cb4 = *reinterpret_cast<const float4*>(&Bb[kk][tx << 2]);
            float ar[4] = {a4.x, a4.y, a4.z, a4.w};
            float br[4] = {ab4.x, ab4.y, ab4.z, ab4.w};
            float cr[4] = {c4.x, c4.y, c4.z, c4.w};
            float dr[4] = {cb4.x, cb4.y, cb4.z, cb4.w};
            #pragma unroll
            for (int i = 0; i < 4; i++)
                #pragma unroll
                for (int j = 0; j < 4; j++) {
                    acca[i][j] += ar[i] * cr[j];
                    accb[i][j] += br[i] * dr[j];
                }
        }
        __syncthreads();
    }
    #pragma unroll
    for (int i = 0; i < 4; i++) {
        int n = bm + (ty << 2) + i;
        if (n >= NEXP) continue;
        float ia = invA[b * NEXP + n];
        float ib = invB[b * NEXP + n];
        int qi = nidx[b * NEXP + n];
        int d0 = bn + (tx << 2);
        float4 bias4 = *reinterpret_cast<const float4*>(btab + (size_t)qi * DM + d0);
        size_t off = ((size_t)b * NEXP + n) * DM + d0;
        float4 oa = make_float4(acca[i][0] * ia + bias4.x, acca[i][1] * ia + bias4.y,
                                acca[i][2] * ia + bias4.z, acca[i][3] * ia + bias4.w);
        float4 ob = make_float4(accb[i][0] * ib + bias4.x, accb[i][1] * ib + bias4.y,
                                accb[i][2] * ib + bias4.z, accb[i][3] * ib + bias4.w);
        *reinterpret_cast<float4*>(CA + off) = oa;
        *reinterpret_cast<float4*>(CB + off) = ob;
    }
}

// ------------------------- backward class GEMM (dual, sel-blend + residual fused) -------------------------
// X1[b,l,d] = x + sel*(invA[b,l]*sum_n m?relu(z):0 * CA[b,n,d]) + (1-sel)*(...CB...)
__global__ void __launch_bounds__(256) classbw(
    const float* __restrict__ Z, const int* __restrict__ mask,
    const float* __restrict__ CA, const float* __restrict__ CB,
    const float* __restrict__ invA, const float* __restrict__ invB,
    const float* __restrict__ SELp, const float* __restrict__ X,
    float* __restrict__ X1)
{
    __shared__ float Aa[16][64], Ab[16][64];
    __shared__ float Ba[16][64], Bb[16][64];
    int tid = threadIdx.x;
    int b  = blockIdx.z;
    int bl = blockIdx.y * 64;   // l
    int bn = blockIdx.x * 64;   // d
    int tx = tid & 15, ty = tid >> 4;
    int nrow = tid >> 4, l4 = (tid & 15) << 2;
    int bkr = tid >> 4, bcq = (tid & 15) << 2;
    const float* Zp = Z + ((size_t)b * NEXP + nrow) * LEN + bl + l4;
    const int*  Mp = mask + ((size_t)b * NEXP + nrow) * LEN + bl + l4;
    const float* CAp = CA + ((size_t)b * NEXP + bkr) * DM + bn + bcq;
    const float* CBp = CB + ((size_t)b * NEXP + bkr) * DM + bn + bcq;
    float acca[4][4] = {}, accb[4][4] = {};
    for (int k0 = 0; k0 < NEXP; k0 += 16) {
        float4 zv = *reinterpret_cast<const float4*>(Zp + (size_t)k0 * LEN);
        int4  mv = *reinterpret_cast<const int4*>(Mp + (size_t)k0 * LEN);
        float4 fa, fb;
        fa.x = mv.x ? fmaxf(zv.x, 0.f) : 0.f;  fb.x = mv.x ? fmaxf(-zv.x, 0.f) : 0.f;
        fa.y = mv.y ? fmaxf(zv.y, 0.f) : 0.f;  fb.y = mv.y ? fmaxf(-zv.y, 0.f) : 0.f;
        fa.z = mv.z ? fmaxf(zv.z, 0.f) : 0.f;  fb.z = mv.z ? fmaxf(-zv.z, 0.f) : 0.f;
        fa.w = mv.w ? fmaxf(zv.w, 0.f) : 0.f;  fb.w = mv.w ? fmaxf(-zv.w, 0.f) : 0.f;
        *reinterpret_cast<float4*>(&Aa[nrow][l4]) = fa;
        *reinterpret_cast<float4*>(&Ab[nrow][l4]) = fb;
        *reinterpret_cast<float4*>(&Ba[bkr][bcq]) = *reinterpret_cast<const float4*>(CAp + (size_t)k0 * DM);
        *reinterpret_cast<float4*>(&Bb[bkr][bcq]) = *reinterpret_cast<const float4*>(CBp + (size_t)k0 * DM);
        __syncthreads();
        #pragma unroll
        for (int kk = 0; kk < 16; kk++) {
            float4 a4  = *reinterpret_cast<const float4*>(&Aa[kk][ty << 2]);
            float4 ab4 = *reinterpret_cast<const float4*>(&Ab[kk][ty << 2]);
            float4 c4  = *reinterpret_cast<const float4*>(&Ba[kk][tx << 2]);
            float4 cb4 = *reinterpret_cast<const float4*>(&Bb[kk][tx << 2]);
            float ar[4] = {a4.x, a4.y, a4.z, a4.w};
            float br[4] = {ab4.x, ab4.y, ab4.z, ab4.w};
            float cr[4] = {c4.x, c4.y, c4.z, c4.w};
            float dr[4] = {cb4.x, cb4.y, cb4.z, cb4.w};
            #pragma unroll
            for (int i = 0; i < 4; i++)
                #pragma unroll
                for (int j = 0; j < 4; j++) {
                    acca[i][j] += ar[i] * cr[j];
                    accb[i][j] += br[i] * dr[j];
                }
        }
        __syncthreads();
    }
    #pragma unroll
    for (int i = 0; i < 4; i++) {
        int l = bl + (ty << 2) + i;
        float ia = invA[b * LEN + l];
        float ib = invB[b * LEN + l];
        size_t off = ((size_t)b * LEN + l) * DM + bn + (tx << 2);
        float4 s4 = *reinterpret_cast<const float4*>(SELp + off);
        float4 x4 = *reinterpret_cast<const float4*>(X + off);
        float4 o;
        o.x = x4.x + s4.x * (acca[i][0] * ia) + (1.f - s4.x) * (accb[i][0] * ib);
        o.y = x4.y + s4.y * (acca[i][1] * ia) + (1.f - s4.y) * (accb[i][1] * ib);
        o.z = x4.z + s4.z * (acca[i][2] * ia) + (1.f - s4.z) * (accb[i][2] * ib);
        o.w = x4.w + s4.w * (acca[i][3] * ia) + (1.f - s4.w) * (accb[i][3] * ib);
        *reinterpret_cast<float4*>(X1 + off) = o;
    }
}

// ------------------------- launch -------------------------
extern "C" void kernel_launch(void* const* d_in, const int* in_sizes, int n_in,
                              void* d_out, int out_size)
{
    const float* x     = (const float*)d_in[0];
    const int*   nidx  = (const int*)d_in[1];
    const int*   mask  = (const int*)d_in[2];
    const float* ln1_g = (const float*)d_in[3];
    const float* ln1_b = (const float*)d_in[4];
    const float* ln2_g = (const float*)d_in[5];
    const float* ln2_b = (const float*)d_in[6];
    const float* q_tab = (const float*)d_in[7];
    const float* b_tab = (const float*)d_in[8];
    const float* Wk  = (const float*)d_in[9];  const float* bk   = (const float*)d_in[10];
    const float* Wa  = (const float*)d_in[11]; const float* ba   = (const float*)d_in[12];
    const float* Wa1 = (const float*)d_in[13]; const float* ba1  = (const float*)d_in[14];
    const float* Wb  = (const float*)d_in[15]; const float* bb   = (const float*)d_in[16];
    const float* Wb1 = (const float*)d_in[17]; const float* bb1  = (const float*)d_in[18];
    const float* Ws  = (const float*)d_in[19]; const float* bsel = (const float*)d_in[20];
    const float* Wf1 = (const float*)d_in[21]; const float* bf1  = (const float*)d_in[22];
    const float* Wf2 = (const float*)d_in[23]; const float* bf2  = (const float*)d_in[24];
    float* out = (float*)d_out;

    float *pX2, *pXK, *pEA0, *pEB0, *pAE, *pBE, *pSEL, *pX1, *pZ, *pCA, *pCB, *pH;
    float *pIAf, *pIBf, *pPA, *pPB, *pIAb, *pIBb;
    cudaGetSymbolAddress((void**)&pX2, g_X2);
    cudaGetSymbolAddress((void**)&pXK, g_XK);
    cudaGetSymbolAddress((void**)&pEA0, g_EA0);
    cudaGetSymbolAddress((void**)&pEB0, g_EB0);
    cudaGetSymbolAddress((void**)&pAE, g_AE);
    cudaGetSymbolAddress((void**)&pBE, g_BE);
    cudaGetSymbolAddress((void**)&pSEL, g_SEL);
    cudaGetSymbolAddress((void**)&pX1, g_X1);
    cudaGetSymbolAddress((void**)&pZ, g_Z);
    cudaGetSymbolAddress((void**)&pCA, g_CA);
    cudaGetSymbolAddress((void**)&pCB, g_CB);
    cudaGetSymbolAddress((void**)&pH, g_H);
    cudaGetSymbolAddress((void**)&pIAf, g_IAf);
    cudaGetSymbolAddress((void**)&pIBf, g_IBf);
    cudaGetSymbolAddress((void**)&pPA, g_PA);
    cudaGetSymbolAddress((void**)&pPB, g_PB);
    cudaGetSymbolAddress((void**)&pIAb, g_IAb);
    cudaGetSymbolAddress((void**)&pIBb, g_IBb);

    // 1. LN1
    ln_kernel<<<M1, 128>>>(x, ln1_g, ln1_b, pX2);

    // 2. dense projections of x2
    dim3 gA(DM / 64, M1 / 64);
    sgemm_nn<0><<<gA, 256>>>(pX2, Wk, bk, nullptr, pXK, M1, DM, DM);
    sgemm_nn<0><<<gA, 256>>>(pX2, Wa, ba, nullptr, pEA0, M1, DM, DM);
    sgemm_nn<0><<<gA, 256>>>(pX2, Wb, bb, nullptr, pEB0, M1, DM, DM);
    sgemm_nn<1><<<gA, 256>>>(pX2, Ws, bsel, nullptr, pSEL, M1, DM, DM);
    sgemm_nn<3><<<gA, 256>>>(pEA0, Wa1, ba1, pEA0, pAE, M1, DM, DM);
    sgemm_nn<3><<<gA, 256>>>(pEB0, Wb1, bb1, pEB0, pBE, M1, DM, DM);

    // 3. z = Q_exp @ x_key^T / sqrt(d)
    zgemm<<<dim3(LEN / 64, (NEXP + 63) / 64, BSZ), 256>>>(nidx, q_tab, pXK, pZ);

    // 4. normalization sums
    fw_sums<<<(BSZ * NEXP) / 8, 256>>>(pZ, mask, pIAf, pIBf);
    bw_partial<<<dim3(BSZ, NSPLIT), LEN>>>(pZ, mask, pPA, pPB);
    bw_final<<<BSZ, LEN>>>(pPA, pPB, pIAb, pIBb);

    // 5. forward classes (dual), 6. backward classes + blend + residual
    classfw<<<dim3(DM / 64, (NEXP + 63) / 64, BSZ), 256>>>(pZ, mask, pAE, pBE, pIAf, pIBf,
                                                           nidx, b_tab, pCA, pCB);
    classbw<<<dim3(DM / 64, LEN / 64, BSZ), 256>>>(pZ, mask, pCA, pCB, pIAb, pIBb,
                                                   pSEL, x, pX1);

    // 7. LN2 + FFN (residual fused into final store)
    ln_kernel<<<M1, 128>>>(pX1, ln2_g, ln2_b, pX2);
    sgemm_nn<2><<<dim3(DFF / 64, M1 / 64), 256>>>(pX2, Wf1, bf1, nullptr, pH, M1, DFF, DM);
    sgemm_nn<4><<<dim3(DM / 64, M1 / 64), 256>>>(pH, Wf2, bf2, pX1, out, M1, DM, DFF);
}

// round 2
// speedup vs baseline: 1.7972x; 1.7972x over previous
#include <cuda_runtime.h>
#include <math.h>
#include <stdint.h>

#define BSZ  64
#define LEN  256
#define DM   512
#define DFF  2048
#define NEXP 992
#define M1   (BSZ * LEN)            // 16384
#define NSPLIT 8
#define ZSCALE 0.044194173824159216f   // 1/sqrt(512)

// GEMM tiling
#define GBM 128
#define GBN 128
#define GBK 16
#define AST 20    // As row stride (floats): 16 + 4 pad
#define BST 132   // Bs row stride (floats): 128 + 4 pad

// ------------------------- scratch (static device globals) -------------------------
static __device__ float g_X2  [(size_t)M1 * DM];
static __device__ float g_XK  [(size_t)M1 * DM];
static __device__ float g_EA0 [(size_t)M1 * DM];
static __device__ float g_EB0 [(size_t)M1 * DM];
static __device__ float g_AE  [(size_t)M1 * DM];
static __device__ float g_BE  [(size_t)M1 * DM];
static __device__ float g_SEL [(size_t)M1 * DM];
static __device__ float g_X1  [(size_t)M1 * DM];
static __device__ float g_Z   [(size_t)BSZ * NEXP * LEN];
static __device__ float g_CA  [(size_t)BSZ * NEXP * DM];
static __device__ float g_CB  [(size_t)BSZ * NEXP * DM];
static __device__ float g_H   [(size_t)M1 * DFF];
static __device__ float g_IAf [BSZ * NEXP];
static __device__ float g_IBf [BSZ * NEXP];
static __device__ float g_PA  [BSZ * NSPLIT * LEN];
static __device__ float g_PB  [BSZ * NSPLIT * LEN];
static __device__ float g_IAb [BSZ * LEN];
static __device__ float g_IBb [BSZ * LEN];
static __device__ float g_WR  [3670016];        // rounded weights
static __device__ float g_QR  [(size_t)NEXP * DM]; // rounded q_tab

// ------------------------- helpers -------------------------
__device__ __forceinline__ float rna(float x) {
    uint32_t u;
    asm("cvt.rna.tf32.f32 %0, %1;" : "=r"(u) : "f"(x));
    return __uint_as_float(u);
}

__device__ __forceinline__ void cpa16(uint32_t dst, const void* src) {
    asm volatile("cp.async.cg.shared.global [%0], [%1], 16;" :: "r"(dst), "l"(src));
}

__device__ __forceinline__ void mma8(float* d, const uint32_t* a, const uint32_t* b) {
    asm volatile(
        "mma.sync.aligned.m16n8k8.row.col.f32.tf32.tf32.f32 "
        "{%0,%1,%2,%3}, {%4,%5,%6,%7}, {%8,%9}, {%0,%1,%2,%3};"
        : "+f"(d[0]), "+f"(d[1]), "+f"(d[2]), "+f"(d[3])
        : "r"(a[0]), "r"(a[1]), "r"(a[2]), "r"(a[3]), "r"(b[0]), "r"(b[1]));
}

// round-to-tf32 elementwise pass (float4 granularity)
__global__ void rnd_kernel(const float* __restrict__ s, float* __restrict__ d, int n4)
{
    int i = blockIdx.x * blockDim.x + threadIdx.x;
    if (i < n4) {
        float4 v = reinterpret_cast<const float4*>(s)[i];
        v.x = rna(v.x); v.y = rna(v.y); v.z = rna(v.z); v.w = rna(v.w);
        reinterpret_cast<float4*>(d)[i] = v;
    }
}

// ------------------------- LayerNorm (optionally tf32-rounded output) -------------------------
template <bool RND>
__global__ void ln_kernel(const float* __restrict__ X, const float* __restrict__ G,
                          const float* __restrict__ B, float* __restrict__ O)
{
    __shared__ float sred[4];
    int row = blockIdx.x;
    int t = threadIdx.x;                       // 128 threads, 4 floats each
    const float4 v = reinterpret_cast<const float4*>(X + (size_t)row * DM)[t];
    float s = v.x + v.y + v.z + v.w;
    #pragma unroll
    for (int o = 16; o; o >>= 1) s += __shfl_down_sync(0xffffffffu, s, o);
    if ((t & 31) == 0) sred[t >> 5] = s;
    __syncthreads();
    float mu = (sred[0] + sred[1] + sred[2] + sred[3]) * (1.0f / DM);
    __syncthreads();
    float4 d;
    d.x = v.x - mu; d.y = v.y - mu; d.z = v.z - mu; d.w = v.w - mu;
    float ss = d.x * d.x + d.y * d.y + d.z * d.z + d.w * d.w;
    #pragma unroll
    for (int o = 16; o; o >>= 1) ss += __shfl_down_sync(0xffffffffu, ss, o);
    if ((t & 31) == 0) sred[t >> 5] = ss;
    __syncthreads();
    float var = (sred[0] + sred[1] + sred[2] + sred[3]) * (1.0f / DM);
    float rstd = rsqrtf(var + 1e-5f);
    const float4 g4 = reinterpret_cast<const float4*>(G)[t];
    const float4 b4 = reinterpret_cast<const float4*>(B)[t];
    float4 o4;
    o4.x = d.x * rstd * g4.x + b4.x;
    o4.y = d.y * rstd * g4.y + b4.y;
    o4.z = d.z * rstd * g4.z + b4.z;
    o4.w = d.w * rstd * g4.w + b4.w;
    if (RND) { o4.x = rna(o4.x); o4.y = rna(o4.y); o4.z = rna(o4.z); o4.w = rna(o4.w); }
    reinterpret_cast<float4*>(O + (size_t)row * DM)[t] = o4;
}

// ------------------------- tf32 tensor-core NN GEMM (128x128x16, mma.m16n8k8) -------------------------
// MODE 0: C = acc + bias
// MODE 1: C = sigmoid(acc + bias)
// MODE 2: C = relu(acc + bias)
// MODE 3: C = Dm * sigmoid(acc + bias)
// MODE 4: C = Dm + acc + bias
// RND: round stored values to tf32 (for outputs feeding later tensor GEMMs)
template <int MODE, bool RND>
__global__ void __launch_bounds__(256) gemm_tf32(
    const float* __restrict__ A, const float* __restrict__ B,
    const float* __restrict__ bias, const float* __restrict__ Dm,
    float* __restrict__ C, int M, int N, int K)
{
    __shared__ float As[2][GBM * AST];
    __shared__ float Bs[2][GBK * BST];
    int tid = threadIdx.x;
    int bm = blockIdx.y * GBM, bn = blockIdx.x * GBN;
    int warp = tid >> 5, lane = tid & 31;
    int wr = warp >> 1, wc = warp & 1;
    int g = lane >> 2, t4 = lane & 3;

    float acc[2][8][4];
    #pragma unroll
    for (int c = 0; c < 2; c++)
        #pragma unroll
        for (int nb = 0; nb < 8; nb++)
            #pragma unroll
            for (int i = 0; i < 4; i++) acc[c][nb][i] = 0.f;

    int KT = K / GBK;

    // async tile load
    auto loadtile = [&](int s, int k0) {
        #pragma unroll
        for (int h = 0; h < 2; h++) {
            int q = tid + h * 256;
            int r = q >> 2, c = (q & 3) << 2;
            uint32_t da = (uint32_t)__cvta_generic_to_shared(&As[s][r * AST + c]);
            cpa16(da, A + (size_t)(bm + r) * K + k0 + c);
            int rb = q >> 5, cb = (q & 31) << 2;
            uint32_t db = (uint32_t)__cvta_generic_to_shared(&Bs[s][rb * BST + cb]);
            cpa16(db, B + (size_t)(k0 + rb) * N + bn + cb);
        }
        asm volatile("cp.async.commit_group;");
    };

    auto compute = [&](int s) {
        #pragma unroll
        for (int kk = 0; kk < GBK; kk += 8) {
            uint32_t a[2][4], b[8][2];
            #pragma unroll
            for (int c = 0; c < 2; c++) {
                const float* ap = &As[s][(wr * 32 + c * 16 + g) * AST + kk + t4];
                a[c][0] = __float_as_uint(ap[0]);
                a[c][1] = __float_as_uint(ap[8 * AST]);
                a[c][2] = __float_as_uint(ap[4]);
                a[c][3] = __float_as_uint(ap[8 * AST + 4]);
            }
            #pragma unroll
            for (int nb = 0; nb < 8; nb++) {
                const float* bp = &Bs[s][(kk + t4) * BST + wc * 64 + nb * 8 + g];
                b[nb][0] = __float_as_uint(bp[0]);
                b[nb][1] = __float_as_uint(bp[4 * BST]);
            }
            #pragma unroll
            for (int c = 0; c < 2; c++)
                #pragma unroll
                for (int nb = 0; nb < 8; nb++)
                    mma8(acc[c][nb], a[c], b[nb]);
        }
    };

    loadtile(0, 0);
    for (int t = 0; t < KT; t++) {
        if (t + 1 < KT) {
            loadtile((t + 1) & 1, (t + 1) * GBK);
            asm volatile("cp.async.wait_group 1;");
        } else {
            asm volatile("cp.async.wait_group 0;");
        }
        __syncthreads();
        compute(t & 1);
        __syncthreads();
    }

    // epilogue
    #pragma unroll
    for (int c = 0; c < 2; c++) {
        #pragma unroll
        for (int nb = 0; nb < 8; nb++) {
            int n = bn + wc * 64 + nb * 8 + 2 * t4;
            float2 bi = *reinterpret_cast<const float2*>(bias + n);
            #pragma unroll
            for (int h = 0; h < 2; h++) {
                int m = bm + wr * 32 + c * 16 + g + h * 8;
                size_t off = (size_t)m * N + n;
                float v0 = acc[c][nb][h * 2 + 0] + bi.x;
                float v1 = acc[c][nb][h * 2 + 1] + bi.y;
                float2 o;
                if (MODE == 0) {
                    o.x = v0; o.y = v1;
                } else if (MODE == 1) {
                    o.x = 1.f / (1.f + expf(-v0)); o.y = 1.f / (1.f + expf(-v1));
                } else if (MODE == 2) {
                    o.x = fmaxf(v0, 0.f); o.y = fmaxf(v1, 0.f);
                } else if (MODE == 3) {
                    float2 d2 = *reinterpret_cast<const float2*>(Dm + off);
                    o.x = d2.x / (1.f + expf(-v0)); o.y = d2.y / (1.f + expf(-v1));
                } else { // MODE 4
                    float2 d2 = *reinterpret_cast<const float2*>(Dm + off);
                    o.x = d2.x + v0; o.y = d2.y + v1;
                }
                if (RND) { o.x = rna(o.x); o.y = rna(o.y); }
                *reinterpret_cast<float2*>(C + off) = o;
            }
        }
    }
}

// ------------------------- z = gather(q_tab) @ XK^T * scale, tf32 tensor cores -------------------------
// A = q_tab_rounded[nidx[b,n]]  (m=n-expert, k=d), B = XK[b,l,:]^T  (k=d, n=l)
__global__ void __launch_bounds__(256) zgemm_tf32(
    const int* __restrict__ nidx, const float* __restrict__ qr,
    const float* __restrict__ XK, float* __restrict__ Z)
{
    __shared__ float As[2][GBM * AST];
    __shared__ float Bs[2][GBK * BST];
    __shared__ int sidx[GBM];
    int tid = threadIdx.x;
    int b  = blockIdx.z;
    int bm = blockIdx.y * GBM;   // n (expert)
    int bl = blockIdx.x * GBN;   // l
    int warp = tid >> 5, lane = tid & 31;
    int wr = warp >> 1, wc = warp & 1;
    int g = lane >> 2, t4 = lane & 3;

    if (tid < GBM) {
        int n = bm + tid;
        sidx[tid] = nidx[b * NEXP + (n < NEXP ? n : NEXP - 1)];
    }
    __syncthreads();

    float acc[2][8][4];
    #pragma unroll
    for (int c = 0; c < 2; c++)
        #pragma unroll
        for (int nb = 0; nb < 8; nb++)
            #pragma unroll
            for (int i = 0; i < 4; i++) acc[c][nb][i] = 0.f;

    float4 ra[2], rb[2];
    auto loadregs = [&](int k0) {
        #pragma unroll
        for (int h = 0; h < 2; h++) {
            int q = tid + h * 256;
            int r = q >> 2, c = (q & 3) << 2;
            ra[h] = *reinterpret_cast<const float4*>(qr + (size_t)sidx[r] * DM + k0 + c);
            rb[h] = *reinterpret_cast<const float4*>(XK + (size_t)(b * LEN + bl + r) * DM + k0 + c);
        }
    };
    auto storeregs = [&](int s) {
        #pragma unroll
        for (int h = 0; h < 2; h++) {
            int q = tid + h * 256;
            int r = q >> 2, c = (q & 3) << 2;
            *reinterpret_cast<float4*>(&As[s][r * AST + c]) = ra[h];
            // transpose B into [k][l]
            Bs[s][(c + 0) * BST + r] = rb[h].x;
            Bs[s][(c + 1) * BST + r] = rb[h].y;
            Bs[s][(c + 2) * BST + r] = rb[h].z;
            Bs[s][(c + 3) * BST + r] = rb[h].w;
        }
    };
    auto compute = [&](int s) {
        #pragma unroll
        for (int kk = 0; kk < GBK; kk += 8) {
            uint32_t a[2][4], bfr[8][2];
            #pragma unroll
            for (int c = 0; c < 2; c++) {
                const float* ap = &As[s][(wr * 32 + c * 16 + g) * AST + kk + t4];
                a[c][0] = __float_as_uint(ap[0]);
                a[c][1] = __float_as_uint(ap[8 * AST]);
                a[c][2] = __float_as_uint(ap[4]);
                a[c][3] = __float_as_uint(ap[8 * AST + 4]);
            }
            #pragma unroll
            for (int nb = 0; nb < 8; nb++) {
                const float* bp = &Bs[s][(kk + t4) * BST + wc * 64 + nb * 8 + g];
                bfr[nb][0] = __float_as_uint(bp[0]);
                bfr[nb][1] = __float_as_uint(bp[4 * BST]);
            }
            #pragma unroll
            for (int c = 0; c < 2; c++)
                #pragma unroll
                for (int nb = 0; nb < 8; nb++)
                    mma8(acc[c][nb], a[c], bfr[nb]);
        }
    };

    int KT = DM / GBK;
    loadregs(0);
    storeregs(0);
    __syncthreads();
    for (int t = 0; t < KT; t++) {
        if (t + 1 < KT) loadregs((t + 1) * GBK);
        compute(t & 1);
        __syncthreads();
        if (t + 1 < KT) {
            storeregs((t + 1) & 1);
            __syncthreads();
        }
    }

    float* Zb = Z + (size_t)b * NEXP * LEN;
    #pragma unroll
    for (int c = 0; c < 2; c++) {
        #pragma unroll
        for (int nb = 0; nb < 8; nb++) {
            int l = bl + wc * 64 + nb * 8 + 2 * t4;
            #pragma unroll
            for (int h = 0; h < 2; h++) {
                int n = bm + wr * 32 + c * 16 + g + h * 8;
                if (n < NEXP) {
                    float2 o;
                    o.x = acc[c][nb][h * 2 + 0] * ZSCALE;
                    o.y = acc[c][nb][h * 2 + 1] * ZSCALE;
                    *reinterpret_cast<float2*>(Zb + (size_t)n * LEN + l) = o;
                }
            }
        }
    }
}

// ------------------------- forward row sums -------------------------
__global__ void fw_sums(const float* __restrict__ Z, const int* __restrict__ mask,
                        float* __restrict__ invA, float* __restrict__ invB)
{
    int gw = (blockIdx.x * blockDim.x + threadIdx.x) >> 5;
    int lane = threadIdx.x & 31;
    if (gw >= BSZ * NEXP) return;
    const float* zr = Z + (size_t)gw * LEN;
    const int* mr = mask + (size_t)gw * LEN;
    float sa = 0.f, sb = 0.f;
    for (int i = lane; i < LEN; i += 32) {
        float z = zr[i];
        if (mr[i]) { sa += fmaxf(z, 0.f); sb += fmaxf(-z, 0.f); }
    }
    #pragma unroll
    for (int o = 16; o; o >>= 1) {
        sa += __shfl_down_sync(0xffffffffu, sa, o);
        sb += __shfl_down_sync(0xffffffffu, sb, o);
    }
    if (!lane) { invA[gw] = 1.f / (sa + 1e-9f); invB[gw] = 1.f / (sb + 1e-9f); }
}

// ------------------------- backward col sums -------------------------
__global__ void bw_partial(const float* __restrict__ Z, const int* __restrict__ mask,
                           float* __restrict__ psA, float* __restrict__ psB)
{
    int b = blockIdx.x, s = blockIdx.y, l = threadIdx.x;
    float sa = 0.f, sb = 0.f;
    int n0 = s * (NEXP / NSPLIT);
    for (int n = n0; n < n0 + NEXP / NSPLIT; n++) {
        size_t off = ((size_t)b * NEXP + n) * LEN + l;
        float z = Z[off];
        if (mask[off]) { sa += fmaxf(z, 0.f); sb += fmaxf(-z, 0.f); }
    }
    psA[((size_t)b * NSPLIT + s) * LEN + l] = sa;
    psB[((size_t)b * NSPLIT + s) * LEN + l] = sb;
}

__global__ void bw_final(const float* __restrict__ psA, const float* __restrict__ psB,
                         float* __restrict__ invA, float* __restrict__ invB)
{
    int b = blockIdx.x, l = threadIdx.x;
    float sa = 0.f, sb = 0.f;
    for (int s = 0; s < NSPLIT; s++) {
        sa += psA[((size_t)b * NSPLIT + s) * LEN + l];
        sb += psB[((size_t)b * NSPLIT + s) * LEN + l];
    }
    invA[b * LEN + l] = 1.f / (sa + 1e-9f);
    invB[b * LEN + l] = 1.f / (sb + 1e-9f);
}

// ------------------------- forward class GEMM (dual a/b, SIMT) -------------------------
__global__ void __launch_bounds__(256) classfw(
    const float* __restrict__ Z, const int* __restrict__ mask,
    const float* __restrict__ AE, const float* __restrict__ BE,
    const float* __restrict__ invA, const float* __restrict__ invB,
    const int* __restrict__ nidx, const float* __restrict__ btab,
    float* __restrict__ CA, float* __restrict__ CB)
{
    __shared__ float Aa[16][64], Ab[16][64];
    __shared__ float Ba[16][64], Bb[16][64];
    int tid = threadIdx.x;
    int b  = blockIdx.z;
    int bm = blockIdx.y * 64;   // n
    int bn = blockIdx.x * 64;   // d
    int tx = tid & 15, ty = tid >> 4;
    int arow = tid >> 2, akq = (tid & 3) << 2;
    int bkr = tid >> 4, bcq = (tid & 15) << 2;
    int an = bm + arow;
    bool avalid = an < NEXP;
    const float* Zp = Z + ((size_t)b * NEXP + (avalid ? an : 0)) * LEN + akq;
    const int*  Mp = mask + ((size_t)b * NEXP + (avalid ? an : 0)) * LEN + akq;
    const float* AEp = AE + ((size_t)b * LEN + bkr) * DM + bn + bcq;
    const float* BEp = BE + ((size_t)b * LEN + bkr) * DM + bn + bcq;
    float acca[4][4] = {}, accb[4][4] = {};
    for (int k0 = 0; k0 < LEN; k0 += 16) {
        float4 zv = avalid ? *reinterpret_cast<const float4*>(Zp + k0) : make_float4(0, 0, 0, 0);
        int4  mv = avalid ? *reinterpret_cast<const int4*>(Mp + k0) : make_int4(0, 0, 0, 0);
        Aa[akq + 0][arow] = mv.x ? fmaxf(zv.x, 0.f) : 0.f;
        Ab[akq + 0][arow] = mv.x ? fmaxf(-zv.x, 0.f) : 0.f;
        Aa[akq + 1][arow] = mv.y ? fmaxf(zv.y, 0.f) : 0.f;
        Ab[akq + 1][arow] = mv.y ? fmaxf(-zv.y, 0.f) : 0.f;
        Aa[akq + 2][arow] = mv.z ? fmaxf(zv.z, 0.f) : 0.f;
        Ab[akq + 2][arow] = mv.z ? fmaxf(-zv.z, 0.f) : 0.f;
        Aa[akq + 3][arow] = mv.w ? fmaxf(zv.w, 0.f) : 0.f;
        Ab[akq + 3][arow] = mv.w ? fmaxf(-zv.w, 0.f) : 0.f;
        *reinterpret_cast<float4*>(&Ba[bkr][bcq]) = *reinterpret_cast<const float4*>(AEp + (size_t)k0 * DM);
        *reinterpret_cast<float4*>(&Bb[bkr][bcq]) = *reinterpret_cast<const float4*>(BEp + (size_t)k0 * DM);
        __syncthreads();
        #pragma unroll
        for (int kk = 0; kk < 16; kk++) {
            float4 a4  = *reinterpret_cast<const float4*>(&Aa[kk][ty << 2]);
            float4 ab4 = *reinterpret_cast<const float4*>(&Ab[kk][ty << 2]);
            float4 c4  = *reinterpret_cast<const float4*>(&Ba[kk][tx << 2]);
            float4 cb4 = *reinterpret_cast<const float4*>(&Bb[kk][tx << 2]);
            float ar[4] = {a4.x, a4.y, a4.z, a4.w};
            float br[4] = {ab4.x, ab4.y, ab4.z, ab4.w};
            float cr[4] = {c4.x, c4.y, c4.z, c4.w};
            float dr[4] = {cb4.x, cb4.y, cb4.z, cb4.w};
            #pragma unroll
            for (int i = 0; i < 4; i++)
                #pragma unroll
                for (int j = 0; j < 4; j++) {
                    acca[i][j] += ar[i] * cr[j];
                    accb[i][j] += br[i] * dr[j];
                }
        }
        __syncthreads();
    }
    #pragma unroll
    for (int i = 0; i < 4; i++) {
        int n = bm + (ty << 2) + i;
        if (n >= NEXP) continue;
        float ia = invA[b * NEXP + n];
        float ib = invB[b * NEXP + n];
        int qi = nidx[b * NEXP + n];
        int d0 = bn + (tx << 2);
        float4 bias4 = *reinterpret_cast<const float4*>(btab + (size_t)qi * DM + d0);
        size_t off = ((size_t)b * NEXP + n) * DM + d0;
        float4 oa = make_float4(acca[i][0] * ia + bias4.x, acca[i][1] * ia + bias4.y,
                                acca[i][2] * ia + bias4.z, acca[i][3] * ia + bias4.w);
        float4 ob = make_float4(accb[i][0] * ib + bias4.x, accb[i][1] * ib + bias4.y,
                                accb[i][2] * ib + bias4.z, accb[i][3] * ib + bias4.w);
        *reinterpret_cast<float4*>(CA + off) = oa;
        *reinterpret_cast<float4*>(CB + off) = ob;
    }
}

// ------------------------- backward class GEMM (dual, sel-blend + residual fused, SIMT) -------------------------
__global__ void __launch_bounds__(256) classbw(
    const float* __restrict__ Z, const int* __restrict__ mask,
    const float* __restrict__ CA, const float* __restrict__ CB,
    const float* __restrict__ invA, const float* __restrict__ invB,
    const float* __restrict__ SELp, const float* __restrict__ X,
    float* __restrict__ X1)
{
    __shared__ float Aa[16][64], Ab[16][64];
    __shared__ float Ba[16][64], Bb[16][64];
    int tid = threadIdx.x;
    int b  = blockIdx.z;
    int bl = blockIdx.y * 64;   // l
    int bn = blockIdx.x * 64;   // d
    int tx = tid & 15, ty = tid >> 4;
    int nrow = tid >> 4, l4 = (tid & 15) << 2;
    int bkr = tid >> 4, bcq = (tid & 15) << 2;
    const float* Zp = Z + ((size_t)b * NEXP + nrow) * LEN + bl + l4;
    const int*  Mp = mask + ((size_t)b * NEXP + nrow) * LEN + bl + l4;
    const float* CAp = CA + ((size_t)b * NEXP + bkr) * DM + bn + bcq;
    const float* CBp = CB + ((size_t)b * NEXP + bkr) * DM + bn + bcq;
    float acca[4][4] = {}, accb[4][4] = {};
    for (int k0 = 0; k0 < NEXP; k0 += 16) {
        float4 zv = *reinterpret_cast<const float4*>(Zp + (size_t)k0 * LEN);
        int4  mv = *reinterpret_cast<const int4*>(Mp + (size_t)k0 * LEN);
        float4 fa, fb;
        fa.x = mv.x ? fmaxf(zv.x, 0.f) : 0.f;  fb.x = mv.x ? fmaxf(-zv.x, 0.f) : 0.f;
        fa.y = mv.y ? fmaxf(zv.y, 0.f) : 0.f;  fb.y = mv.y ? fmaxf(-zv.y, 0.f) : 0.f;
        fa.z = mv.z ? fmaxf(zv.z, 0.f) : 0.f;  fb.z = mv.z ? fmaxf(-zv.z, 0.f) : 0.f;
        fa.w = mv.w ? fmaxf(zv.w, 0.f) : 0.f;  fb.w = mv.w ? fmaxf(-zv.w, 0.f) : 0.f;
        *reinterpret_cast<float4*>(&Aa[nrow][l4]) = fa;
        *reinterpret_cast<float4*>(&Ab[nrow][l4]) = fb;
        *reinterpret_cast<float4*>(&Ba[bkr][bcq]) = *reinterpret_cast<const float4*>(CAp + (size_t)k0 * DM);
        *reinterpret_cast<float4*>(&Bb[bkr][bcq]) = *reinterpret_cast<const float4*>(CBp + (size_t)k0 * DM);
        __syncthreads();
        #pragma unroll
        for (int kk = 0; kk < 16; kk++) {
            float4 a4  = *reinterpret_cast<const float4*>(&Aa[kk][ty << 2]);
            float4 ab4 = *reinterpret_cast<const float4*>(&Ab[kk][ty << 2]);
            float4 c4  = *reinterpret_cast<const float4*>(&Ba[kk][tx << 2]);
            float4 cb4 = *reinterpret_cast<const float4*>(&Bb[kk][tx << 2]);
            float ar[4] = {a4.x, a4.y, a4.z, a4.w};
            float br[4] = {ab4.x, ab4.y, ab4.z, ab4.w};
            float cr[4] = {c4.x, c4.y, c4.z, c4.w};
            float dr[4] = {cb4.x, cb4.y, cb4.z, cb4.w};
            #pragma unroll
            for (int i = 0; i < 4; i++)
                #pragma unroll
                for (int j = 0; j < 4; j++) {
                    acca[i][j] += ar[i] * cr[j];
                    accb[i][j] += br[i] * dr[j];
                }
        }
        __syncthreads();
    }
    #pragma unroll
    for (int i = 0; i < 4; i++) {
        int l = bl + (ty << 2) + i;
        float ia = invA[b * LEN + l];
        float ib = invB[b * LEN + l];
        size_t off = ((size_t)b * LEN + l) * DM + bn + (tx << 2);
        float4 s4 = *reinterpret_cast<const float4*>(SELp + off);
        float4 x4 = *reinterpret_cast<const float4*>(X + off);
        float4 o;
        o.x = x4.x + s4.x * (acca[i][0] * ia) + (1.f - s4.x) * (accb[i][0] * ib);
        o.y = x4.y + s4.y * (acca[i][1] * ia) + (1.f - s4.y) * (accb[i][1] * ib);
        o.z = x4.z + s4.z * (acca[i][2] * ia) + (1.f - s4.z) * (accb[i][2] * ib);
        o.w = x4.w + s4.w * (acca[i][3] * ia) + (1.f - s4.w) * (accb[i][3] * ib);
        *reinterpret_cast<float4*>(X1 + off) = o;
    }
}

// ------------------------- launch -------------------------
extern "C" void kernel_launch(void* const* d_in, const int* in_sizes, int n_in,
                              void* d_out, int out_size)
{
    const float* x     = (const float*)d_in[0];
    const int*   nidx  = (const int*)d_in[1];
    const int*   mask  = (const int*)d_in[2];
    const float* ln1_g = (const float*)d_in[3];
    const float* ln1_b = (const float*)d_in[4];
    const float* ln2_g = (const float*)d_in[5];
    const float* ln2_b = (const float*)d_in[6];
    const float* q_tab = (const float*)d_in[7];
    const float* b_tab = (const float*)d_in[8];
    const float* Wk  = (const float*)d_in[9];  const float* bk   = (const float*)d_in[10];
    const float* Wa  = (const float*)d_in[11]; const float* ba   = (const float*)d_in[12];
    const float* Wa1 = (const float*)d_in[13]; const float* ba1  = (const float*)d_in[14];
    const float* Wb  = (const float*)d_in[15]; const float* bb   = (const float*)d_in[16];
    const float* Wb1 = (const float*)d_in[17]; const float* bb1  = (const float*)d_in[18];
    const float* Ws  = (const float*)d_in[19]; const float* bsel = (const float*)d_in[20];
    const float* Wf1 = (const float*)d_in[21]; const float* bf1  = (const float*)d_in[22];
    const float* Wf2 = (const float*)d_in[23]; const float* bf2  = (const float*)d_in[24];
    float* out = (float*)d_out;

    float *pX2, *pXK, *pEA0, *pEB0, *pAE, *pBE, *pSEL, *pX1, *pZ, *pCA, *pCB, *pH;
    float *pIAf, *pIBf, *pPA, *pPB, *pIAb, *pIBb, *pWR, *pQR;
    cudaGetSymbolAddress((void**)&pX2, g_X2);
    cudaGetSymbolAddress((void**)&pXK, g_XK);
    cudaGetSymbolAddress((void**)&pEA0, g_EA0);
    cudaGetSymbolAddress((void**)&pEB0, g_EB0);
    cudaGetSymbolAddress((void**)&pAE, g_AE);
    cudaGetSymbolAddress((void**)&pBE, g_BE);
    cudaGetSymbolAddress((void**)&pSEL, g_SEL);
    cudaGetSymbolAddress((void**)&pX1, g_X1);
    cudaGetSymbolAddress((void**)&pZ, g_Z);
    cudaGetSymbolAddress((void**)&pCA, g_CA);
    cudaGetSymbolAddress((void**)&pCB, g_CB);
    cudaGetSymbolAddress((void**)&pH, g_H);
    cudaGetSymbolAddress((void**)&pIAf, g_IAf);
    cudaGetSymbolAddress((void**)&pIBf, g_IBf);
    cudaGetSymbolAddress((void**)&pPA, g_PA);
    cudaGetSymbolAddress((void**)&pPB, g_PB);
    cudaGetSymbolAddress((void**)&pIAb, g_IAb);
    cudaGetSymbolAddress((void**)&pIBb, g_IBb);
    cudaGetSymbolAddress((void**)&pWR, g_WR);
    cudaGetSymbolAddress((void**)&pQR, g_QR);

    float* WkR  = pWR;
    float* WaR  = pWR + 262144;
    float* WbR  = pWR + 524288;
    float* WsR  = pWR + 786432;
    float* Wa1R = pWR + 1048576;
    float* Wb1R = pWR + 1310720;
    float* Wf1R = pWR + 1572864;
    float* Wf2R = pWR + 2621440;

    // 0. round weights + q_tab to tf32 (RNA)
    rnd_kernel<<<256, 256>>>(Wk,  WkR,  65536);
    rnd_kernel<<<256, 256>>>(Wa,  WaR,  65536);
    rnd_kernel<<<256, 256>>>(Wb,  WbR,  65536);
    rnd_kernel<<<256, 256>>>(Ws,  WsR,  65536);
    rnd_kernel<<<256, 256>>>(Wa1, Wa1R, 65536);
    rnd_kernel<<<256, 256>>>(Wb1, Wb1R, 65536);
    rnd_kernel<<<1024, 256>>>(Wf1, Wf1R, 262144);
    rnd_kernel<<<1024, 256>>>(Wf2, Wf2R, 262144);
    rnd_kernel<<<496, 256>>>(q_tab, pQR, 126976);

    // 1. LN1 (rounded output -> feeds tensor GEMMs)
    ln_kernel<true><<<M1, 128>>>(x, ln1_g, ln1_b, pX2);

    // 2. dense projections (tf32 tensor cores)
    dim3 gA(DM / GBN, M1 / GBM);
    gemm_tf32<0, true ><<<gA, 256>>>(pX2, WkR, bk, nullptr, pXK, M1, DM, DM);
    gemm_tf32<0, true ><<<gA, 256>>>(pX2, WaR, ba, nullptr, pEA0, M1, DM, DM);
    gemm_tf32<0, true ><<<gA, 256>>>(pX2, WbR, bb, nullptr, pEB0, M1, DM, DM);
    gemm_tf32<1, false><<<gA, 256>>>(pX2, WsR, bsel, nullptr, pSEL, M1, DM, DM);
    gemm_tf32<3, false><<<gA, 256>>>(pEA0, Wa1R, ba1, pEA0, pAE, M1, DM, DM);
    gemm_tf32<3, false><<<gA, 256>>>(pEB0, Wb1R, bb1, pEB0, pBE, M1, DM, DM);

    // 3. z = Q_exp @ XK^T / sqrt(d)   (tf32 tensor cores)
    zgemm_tf32<<<dim3(LEN / GBN, (NEXP + GBM - 1) / GBM, BSZ), 256>>>(nidx, pQR, pXK, pZ);

    // 4. normalization sums
    fw_sums<<<(BSZ * NEXP) / 8, 256>>>(pZ, mask, pIAf, pIBf);
    bw_partial<<<dim3(BSZ, NSPLIT), LEN>>>(pZ, mask, pPA, pPB);
    bw_final<<<BSZ, LEN>>>(pPA, pPB, pIAb, pIBb);

    // 5. forward classes (dual), 6. backward classes + blend + residual (SIMT)
    classfw<<<dim3(DM / 64, (NEXP + 63) / 64, BSZ), 256>>>(pZ, mask, pAE, pBE, pIAf, pIBf,
                                                           nidx, b_tab, pCA, pCB);
    classbw<<<dim3(DM / 64, LEN / 64, BSZ), 256>>>(pZ, mask, pCA, pCB, pIAb, pIBb,
                                                   pSEL, x, pX1);

    // 7. LN2 + FFN (tf32 tensor cores; residual fused into final store)
    ln_kernel<true><<<M1, 128>>>(pX1, ln2_g, ln2_b, pX2);
    gemm_tf32<2, true ><<<dim3(DFF / GBN, M1 / GBM), 256>>>(pX2, Wf1R, bf1, nullptr, pH, M1, DFF, DM);
    gemm_tf32<4, false><<<dim3(DM / GBN, M1 / GBM), 256>>>(pH, Wf2R, bf2, pX1, out, M1, DM, DFF);
}

// round 3
// speedup vs baseline: 2.4648x; 1.3715x over previous
#include <cuda_runtime.h>
#include <math.h>
#include <stdint.h>

#define BSZ  64
#define LEN  256
#define DM   512
#define DFF  2048
#define NEXP 992
#define M1   (BSZ * LEN)            // 16384
#define NSPLIT 8
#define ZSCALE 0.044194173824159216f   // 1/sqrt(512)

// dense GEMM tiling
#define GBM 128
#define GBN 128
#define GBK 16
#define AST 20    // As row stride (floats): 16 + 4 pad
#define BST 132   // Bs row stride (floats): 128 + 4 pad

// class GEMM tiling (128x64 tile, dual accumulators)
#define ASTC 17   // 16 + 1 pad
#define BSTC 68   // 64 + 4 pad

// ------------------------- scratch (static device globals) -------------------------
static __device__ float g_X2  [(size_t)M1 * DM];
static __device__ float g_XK  [(size_t)M1 * DM];
static __device__ float g_EA0 [(size_t)M1 * DM];
static __device__ float g_EB0 [(size_t)M1 * DM];
static __device__ float g_AE  [(size_t)M1 * DM];
static __device__ float g_BE  [(size_t)M1 * DM];
static __device__ float g_SEL [(size_t)M1 * DM];
static __device__ float g_X1  [(size_t)M1 * DM];
static __device__ float g_Z   [(size_t)BSZ * NEXP * LEN];
static __device__ float g_CA  [(size_t)BSZ * NEXP * DM];
static __device__ float g_CB  [(size_t)BSZ * NEXP * DM];
static __device__ float g_H   [(size_t)M1 * DFF];
static __device__ float g_IAf [BSZ * NEXP];
static __device__ float g_IBf [BSZ * NEXP];
static __device__ float g_PA  [BSZ * NSPLIT * LEN];
static __device__ float g_PB  [BSZ * NSPLIT * LEN];
static __device__ float g_IAb [BSZ * LEN];
static __device__ float g_IBb [BSZ * LEN];
static __device__ float g_WR  [3670016];           // rounded weights
static __device__ float g_QR  [(size_t)NEXP * DM]; // rounded q_tab

// ------------------------- helpers -------------------------
__device__ __forceinline__ float rna(float x) {
    uint32_t u;
    asm("cvt.rna.tf32.f32 %0, %1;" : "=r"(u) : "f"(x));
    return __uint_as_float(u);
}

__device__ __forceinline__ void cpa16(uint32_t dst, const void* src) {
    asm volatile("cp.async.cg.shared.global [%0], [%1], 16;" :: "r"(dst), "l"(src));
}

__device__ __forceinline__ void mma8(float* d, const uint32_t* a, const uint32_t* b) {
    asm volatile(
        "mma.sync.aligned.m16n8k8.row.col.f32.tf32.tf32.f32 "
        "{%0,%1,%2,%3}, {%4,%5,%6,%7}, {%8,%9}, {%0,%1,%2,%3};"
        : "+f"(d[0]), "+f"(d[1]), "+f"(d[2]), "+f"(d[3])
        : "r"(a[0]), "r"(a[1]), "r"(a[2]), "r"(a[3]), "r"(b[0]), "r"(b[1]));
}

// round-to-tf32 elementwise pass (float4 granularity)
__global__ void rnd_kernel(const float* __restrict__ s, float* __restrict__ d, int n4)
{
    int i = blockIdx.x * blockDim.x + threadIdx.x;
    if (i < n4) {
        float4 v = reinterpret_cast<const float4*>(s)[i];
        v.x = rna(v.x); v.y = rna(v.y); v.z = rna(v.z); v.w = rna(v.w);
        reinterpret_cast<float4*>(d)[i] = v;
    }
}

// ------------------------- LayerNorm (optionally tf32-rounded output) -------------------------
template <bool RND>
__global__ void ln_kernel(const float* __restrict__ X, const float* __restrict__ G,
                          const float* __restrict__ B, float* __restrict__ O)
{
    __shared__ float sred[4];
    int row = blockIdx.x;
    int t = threadIdx.x;                       // 128 threads, 4 floats each
    const float4 v = reinterpret_cast<const float4*>(X + (size_t)row * DM)[t];
    float s = v.x + v.y + v.z + v.w;
    #pragma unroll
    for (int o = 16; o; o >>= 1) s += __shfl_down_sync(0xffffffffu, s, o);
    if ((t & 31) == 0) sred[t >> 5] = s;
    __syncthreads();
    float mu = (sred[0] + sred[1] + sred[2] + sred[3]) * (1.0f / DM);
    __syncthreads();
    float4 d;
    d.x = v.x - mu; d.y = v.y - mu; d.z = v.z - mu; d.w = v.w - mu;
    float ss = d.x * d.x + d.y * d.y + d.z * d.z + d.w * d.w;
    #pragma unroll
    for (int o = 16; o; o >>= 1) ss += __shfl_down_sync(0xffffffffu, ss, o);
    if ((t & 31) == 0) sred[t >> 5] = ss;
    __syncthreads();
    float var = (sred[0] + sred[1] + sred[2] + sred[3]) * (1.0f / DM);
    float rstd = rsqrtf(var + 1e-5f);
    const float4 g4 = reinterpret_cast<const float4*>(G)[t];
    const float4 b4 = reinterpret_cast<const float4*>(B)[t];
    float4 o4;
    o4.x = d.x * rstd * g4.x + b4.x;
    o4.y = d.y * rstd * g4.y + b4.y;
    o4.z = d.z * rstd * g4.z + b4.z;
    o4.w = d.w * rstd * g4.w + b4.w;
    if (RND) { o4.x = rna(o4.x); o4.y = rna(o4.y); o4.z = rna(o4.z); o4.w = rna(o4.w); }
    reinterpret_cast<float4*>(O + (size_t)row * DM)[t] = o4;
}

// ------------------------- tf32 tensor-core NN GEMM (128x128x16, mma.m16n8k8) -------------------------
template <int MODE, bool RND>
__global__ void __launch_bounds__(256) gemm_tf32(
    const float* __restrict__ A, const float* __restrict__ B,
    const float* __restrict__ bias, const float* __restrict__ Dm,
    float* __restrict__ C, int M, int N, int K)
{
    __shared__ float As[2][GBM * AST];
    __shared__ float Bs[2][GBK * BST];
    int tid = threadIdx.x;
    int bm = blockIdx.y * GBM, bn = blockIdx.x * GBN;
    int warp = tid >> 5, lane = tid & 31;
    int wr = warp >> 1, wc = warp & 1;
    int g = lane >> 2, t4 = lane & 3;

    float acc[2][8][4];
    #pragma unroll
    for (int c = 0; c < 2; c++)
        #pragma unroll
        for (int nb = 0; nb < 8; nb++)
            #pragma unroll
            for (int i = 0; i < 4; i++) acc[c][nb][i] = 0.f;

    int KT = K / GBK;

    auto loadtile = [&](int s, int k0) {
        #pragma unroll
        for (int h = 0; h < 2; h++) {
            int q = tid + h * 256;
            int r = q >> 2, c = (q & 3) << 2;
            uint32_t da = (uint32_t)__cvta_generic_to_shared(&As[s][r * AST + c]);
            cpa16(da, A + (size_t)(bm + r) * K + k0 + c);
            int rb = q >> 5, cb = (q & 31) << 2;
            uint32_t db = (uint32_t)__cvta_generic_to_shared(&Bs[s][rb * BST + cb]);
            cpa16(db, B + (size_t)(k0 + rb) * N + bn + cb);
        }
        asm volatile("cp.async.commit_group;");
    };

    auto compute = [&](int s) {
        #pragma unroll
        for (int kk = 0; kk < GBK; kk += 8) {
            uint32_t a[2][4], b[8][2];
            #pragma unroll
            for (int c = 0; c < 2; c++) {
                const float* ap = &As[s][(wr * 32 + c * 16 + g) * AST + kk + t4];
                a[c][0] = __float_as_uint(ap[0]);
                a[c][1] = __float_as_uint(ap[8 * AST]);
                a[c][2] = __float_as_uint(ap[4]);
                a[c][3] = __float_as_uint(ap[8 * AST + 4]);
            }
            #pragma unroll
            for (int nb = 0; nb < 8; nb++) {
                const float* bp = &Bs[s][(kk + t4) * BST + wc * 64 + nb * 8 + g];
                b[nb][0] = __float_as_uint(bp[0]);
                b[nb][1] = __float_as_uint(bp[4 * BST]);
            }
            #pragma unroll
            for (int c = 0; c < 2; c++)
                #pragma unroll
                for (int nb = 0; nb < 8; nb++)
                    mma8(acc[c][nb], a[c], b[nb]);
        }
    };

    loadtile(0, 0);
    for (int t = 0; t < KT; t++) {
        if (t + 1 < KT) {
            loadtile((t + 1) & 1, (t + 1) * GBK);
            asm volatile("cp.async.wait_group 1;");
        } else {
            asm volatile("cp.async.wait_group 0;");
        }
        __syncthreads();
        compute(t & 1);
        __syncthreads();
    }

    #pragma unroll
    for (int c = 0; c < 2; c++) {
        #pragma unroll
        for (int nb = 0; nb < 8; nb++) {
            int n = bn + wc * 64 + nb * 8 + 2 * t4;
            float2 bi = *reinterpret_cast<const float2*>(bias + n);
            #pragma unroll
            for (int h = 0; h < 2; h++) {
                int m = bm + wr * 32 + c * 16 + g + h * 8;
                size_t off = (size_t)m * N + n;
                float v0 = acc[c][nb][h * 2 + 0] + bi.x;
                float v1 = acc[c][nb][h * 2 + 1] + bi.y;
                float2 o;
                if (MODE == 0) {
                    o.x = v0; o.y = v1;
                } else if (MODE == 1) {
                    o.x = 1.f / (1.f + expf(-v0)); o.y = 1.f / (1.f + expf(-v1));
                } else if (MODE == 2) {
                    o.x = fmaxf(v0, 0.f); o.y = fmaxf(v1, 0.f);
                } else if (MODE == 3) {
                    float2 d2 = *reinterpret_cast<const float2*>(Dm + off);
                    o.x = d2.x / (1.f + expf(-v0)); o.y = d2.y / (1.f + expf(-v1));
                } else { // MODE 4
                    float2 d2 = *reinterpret_cast<const float2*>(Dm + off);
                    o.x = d2.x + v0; o.y = d2.y + v1;
                }
                if (RND) { o.x = rna(o.x); o.y = rna(o.y); }
                *reinterpret_cast<float2*>(C + off) = o;
            }
        }
    }
}

// ------------------------- z = gather(q_tab) @ XK^T * scale, tf32 tensor cores -------------------------
__global__ void __launch_bounds__(256) zgemm_tf32(
    const int* __restrict__ nidx, const float* __restrict__ qr,
    const float* __restrict__ XK, float* __restrict__ Z)
{
    __shared__ float As[2][GBM * AST];
    __shared__ float Bs[2][GBK * BST];
    __shared__ int sidx[GBM];
    int tid = threadIdx.x;
    int b  = blockIdx.z;
    int bm = blockIdx.y * GBM;   // n (expert)
    int bl = blockIdx.x * GBN;   // l
    int warp = tid >> 5, lane = tid & 31;
    int wr = warp >> 1, wc = warp & 1;
    int g = lane >> 2, t4 = lane & 3;

    if (tid < GBM) {
        int n = bm + tid;
        sidx[tid] = nidx[b * NEXP + (n < NEXP ? n : NEXP - 1)];
    }
    __syncthreads();

    float acc[2][8][4];
    #pragma unroll
    for (int c = 0; c < 2; c++)
        #pragma unroll
        for (int nb = 0; nb < 8; nb++)
            #pragma unroll
            for (int i = 0; i < 4; i++) acc[c][nb][i] = 0.f;

    float4 ra[2], rb[2];
    auto loadregs = [&](int k0) {
        #pragma unroll
        for (int h = 0; h < 2; h++) {
            int q = tid + h * 256;
            int r = q >> 2, c = (q & 3) << 2;
            ra[h] = *reinterpret_cast<const float4*>(qr + (size_t)sidx[r] * DM + k0 + c);
            rb[h] = *reinterpret_cast<const float4*>(XK + (size_t)(b * LEN + bl + r) * DM + k0 + c);
        }
    };
    auto storeregs = [&](int s) {
        #pragma unroll
        for (int h = 0; h < 2; h++) {
            int q = tid + h * 256;
            int r = q >> 2, c = (q & 3) << 2;
            *reinterpret_cast<float4*>(&As[s][r * AST + c]) = ra[h];
            Bs[s][(c + 0) * BST + r] = rb[h].x;
            Bs[s][(c + 1) * BST + r] = rb[h].y;
            Bs[s][(c + 2) * BST + r] = rb[h].z;
            Bs[s][(c + 3) * BST + r] = rb[h].w;
        }
    };
    auto compute = [&](int s) {
        #pragma unroll
        for (int kk = 0; kk < GBK; kk += 8) {
            uint32_t a[2][4], bfr[8][2];
            #pragma unroll
            for (int c = 0; c < 2; c++) {
                const float* ap = &As[s][(wr * 32 + c * 16 + g) * AST + kk + t4];
                a[c][0] = __float_as_uint(ap[0]);
                a[c][1] = __float_as_uint(ap[8 * AST]);
                a[c][2] = __float_as_uint(ap[4]);
                a[c][3] = __float_as_uint(ap[8 * AST + 4]);
            }
            #pragma unroll
            for (int nb = 0; nb < 8; nb++) {
                const float* bp = &Bs[s][(kk + t4) * BST + wc * 64 + nb * 8 + g];
                bfr[nb][0] = __float_as_uint(bp[0]);
                bfr[nb][1] = __float_as_uint(bp[4 * BST]);
            }
            #pragma unroll
            for (int c = 0; c < 2; c++)
                #pragma unroll
                for (int nb = 0; nb < 8; nb++)
                    mma8(acc[c][nb], a[c], bfr[nb]);
        }
    };

    int KT = DM / GBK;
    loadregs(0);
    storeregs(0);
    __syncthreads();
    for (int t = 0; t < KT; t++) {
        if (t + 1 < KT) loadregs((t + 1) * GBK);
        compute(t & 1);
        __syncthreads();
        if (t + 1 < KT) {
            storeregs((t + 1) & 1);
            __syncthreads();
        }
    }

    float* Zb = Z + (size_t)b * NEXP * LEN;
    #pragma unroll
    for (int c = 0; c < 2; c++) {
        #pragma unroll
        for (int nb = 0; nb < 8; nb++) {
            int l = bl + wc * 64 + nb * 8 + 2 * t4;
            #pragma unroll
            for (int h = 0; h < 2; h++) {
                int n = bm + wr * 32 + c * 16 + g + h * 8;
                if (n < NEXP) {
                    float2 o;
                    o.x = acc[c][nb][h * 2 + 0] * ZSCALE;
                    o.y = acc[c][nb][h * 2 + 1] * ZSCALE;
                    *reinterpret_cast<float2*>(Zb + (size_t)n * LEN + l) = o;
                }
            }
        }
    }
}

// ------------------------- forward row sums -------------------------
__global__ void fw_sums(const float* __restrict__ Z, const int* __restrict__ mask,
                        float* __restrict__ invA, float* __restrict__ invB)
{
    int gw = (blockIdx.x * blockDim.x + threadIdx.x) >> 5;
    int lane = threadIdx.x & 31;
    if (gw >= BSZ * NEXP) return;
    const float* zr = Z + (size_t)gw * LEN;
    const int* mr = mask + (size_t)gw * LEN;
    float sa = 0.f, sb = 0.f;
    for (int i = lane; i < LEN; i += 32) {
        float z = zr[i];
        if (mr[i]) { sa += fmaxf(z, 0.f); sb += fmaxf(-z, 0.f); }
    }
    #pragma unroll
    for (int o = 16; o; o >>= 1) {
        sa += __shfl_down_sync(0xffffffffu, sa, o);
        sb += __shfl_down_sync(0xffffffffu, sb, o);
    }
    if (!lane) { invA[gw] = 1.f / (sa + 1e-9f); invB[gw] = 1.f / (sb + 1e-9f); }
}

// ------------------------- backward col sums -------------------------
__global__ void bw_partial(const float* __restrict__ Z, const int* __restrict__ mask,
                           float* __restrict__ psA, float* __restrict__ psB)
{
    int b = blockIdx.x, s = blockIdx.y, l = threadIdx.x;
    float sa = 0.f, sb = 0.f;
    int n0 = s * (NEXP / NSPLIT);
    for (int n = n0; n < n0 + NEXP / NSPLIT; n++) {
        size_t off = ((size_t)b * NEXP + n) * LEN + l;
        float z = Z[off];
        if (mask[off]) { sa += fmaxf(z, 0.f); sb += fmaxf(-z, 0.f); }
    }
    psA[((size_t)b * NSPLIT + s) * LEN + l] = sa;
    psB[((size_t)b * NSPLIT + s) * LEN + l] = sb;
}

__global__ void bw_final(const float* __restrict__ psA, const float* __restrict__ psB,
                         float* __restrict__ invA, float* __restrict__ invB)
{
    int b = blockIdx.x, l = threadIdx.x;
    float sa = 0.f, sb = 0.f;
    for (int s = 0; s < NSPLIT; s++) {
        sa += psA[((size_t)b * NSPLIT + s) * LEN + l];
        sb += psB[((size_t)b * NSPLIT + s) * LEN + l];
    }
    invA[b * LEN + l] = 1.f / (sa + 1e-9f);
    invB[b * LEN + l] = 1.f / (sb + 1e-9f);
}

// ------------------------- forward class GEMM, tf32 dual (128x64 tile) -------------------------
// CA[b,n,d] = invA[b,n] * sum_l (m ? relu(z[n,l]) : 0) * AE[b,l,d] + b_tab[idx[b,n],d]
__global__ void __launch_bounds__(256) classfw_tf32(
    const float* __restrict__ Z, const int* __restrict__ mask,
    const float* __restrict__ AE, const float* __restrict__ BE,
    const float* __restrict__ invA, const float* __restrict__ invB,
    const int* __restrict__ nidx, const float* __restrict__ btab,
    float* __restrict__ CA, float* __restrict__ CB)
{
    __shared__ float Aa[128 * ASTC], Ab[128 * ASTC];
    __shared__ float Ba[16 * BSTC], Bb[16 * BSTC];
    int tid = threadIdx.x;
    int b  = blockIdx.z;
    int bm = blockIdx.y * 128;   // expert n
    int bn = blockIdx.x * 64;    // d
    int warp = tid >> 5, lane = tid & 31;
    int wr = warp >> 1, wc = warp & 1;
    int g = lane >> 2, t4 = lane & 3;

    float acca[2][4][4] = {}, accb[2][4][4] = {};

    float4 za[2]; int4 ma[2]; float4 ea, eb;
    int rb = tid >> 4, cb = (tid & 15) << 2;

    auto loadregs = [&](int k0) {
        #pragma unroll
        for (int h = 0; h < 2; h++) {
            int q = tid + h * 256;
            int r = q >> 2, c = (q & 3) << 2;
            int n = bm + r; if (n >= NEXP) n = NEXP - 1;
            size_t zoff = ((size_t)b * NEXP + n) * LEN + k0 + c;
            za[h] = *reinterpret_cast<const float4*>(Z + zoff);
            ma[h] = *reinterpret_cast<const int4*>(mask + zoff);
        }
        size_t eoff = ((size_t)b * LEN + k0 + rb) * DM + bn + cb;
        ea = *reinterpret_cast<const float4*>(AE + eoff);
        eb = *reinterpret_cast<const float4*>(BE + eoff);
    };
    auto storeregs = [&]() {
        #pragma unroll
        for (int h = 0; h < 2; h++) {
            int q = tid + h * 256;
            int r = q >> 2, c = (q & 3) << 2;
            float* pa = &Aa[r * ASTC + c];
            float* pb = &Ab[r * ASTC + c];
            pa[0] = ma[h].x ? rna(fmaxf(za[h].x, 0.f)) : 0.f;
            pb[0] = ma[h].x ? rna(fmaxf(-za[h].x, 0.f)) : 0.f;
            pa[1] = ma[h].y ? rna(fmaxf(za[h].y, 0.f)) : 0.f;
            pb[1] = ma[h].y ? rna(fmaxf(-za[h].y, 0.f)) : 0.f;
            pa[2] = ma[h].z ? rna(fmaxf(za[h].z, 0.f)) : 0.f;
            pb[2] = ma[h].z ? rna(fmaxf(-za[h].z, 0.f)) : 0.f;
            pa[3] = ma[h].w ? rna(fmaxf(za[h].w, 0.f)) : 0.f;
            pb[3] = ma[h].w ? rna(fmaxf(-za[h].w, 0.f)) : 0.f;
        }
        *reinterpret_cast<float4*>(&Ba[rb * BSTC + cb]) = ea;
        *reinterpret_cast<float4*>(&Bb[rb * BSTC + cb]) = eb;
    };
    auto compute = [&]() {
        #pragma unroll
        for (int kk = 0; kk < 16; kk += 8) {
            uint32_t afa[2][4], afb[2][4], bfa[4][2], bfb[4][2];
            #pragma unroll
            for (int c = 0; c < 2; c++) {
                const float* ap = &Aa[(wr * 32 + c * 16 + g) * ASTC + kk + t4];
                const float* bp = &Ab[(wr * 32 + c * 16 + g) * ASTC + kk + t4];
                afa[c][0] = __float_as_uint(ap[0]);
                afa[c][1] = __float_as_uint(ap[8 * ASTC]);
                afa[c][2] = __float_as_uint(ap[4]);
                afa[c][3] = __float_as_uint(ap[8 * ASTC + 4]);
                afb[c][0] = __float_as_uint(bp[0]);
                afb[c][1] = __float_as_uint(bp[8 * ASTC]);
                afb[c][2] = __float_as_uint(bp[4]);
                afb[c][3] = __float_as_uint(bp[8 * ASTC + 4]);
            }
            #pragma unroll
            for (int nb = 0; nb < 4; nb++) {
                const float* bpa = &Ba[(kk + t4) * BSTC + wc * 32 + nb * 8 + g];
                const float* bpb = &Bb[(kk + t4) * BSTC + wc * 32 + nb * 8 + g];
                bfa[nb][0] = __float_as_uint(bpa[0]);
                bfa[nb][1] = __float_as_uint(bpa[4 * BSTC]);
                bfb[nb][0] = __float_as_uint(bpb[0]);
                bfb[nb][1] = __float_as_uint(bpb[4 * BSTC]);
            }
            #pragma unroll
            for (int c = 0; c < 2; c++)
                #pragma unroll
                for (int nb = 0; nb < 4; nb++) {
                    mma8(acca[c][nb], afa[c], bfa[nb]);
                    mma8(accb[c][nb], afb[c], bfb[nb]);
                }
        }
    };

    loadregs(0);
    storeregs();
    __syncthreads();
    const int KT = LEN / 16;   // 16
    for (int t = 0; t < KT; t++) {
        if (t + 1 < KT) loadregs((t + 1) * 16);
        compute();
        __syncthreads();
        if (t + 1 < KT) { storeregs(); __syncthreads(); }
    }

    #pragma unroll
    for (int c = 0; c < 2; c++) {
        #pragma unroll
        for (int h = 0; h < 2; h++) {
            int n = bm + wr * 32 + c * 16 + g + h * 8;
            if (n >= NEXP) continue;
            float ia = invA[b * NEXP + n];
            float ib = invB[b * NEXP + n];
            int qi = nidx[b * NEXP + n];
            #pragma unroll
            for (int nb = 0; nb < 4; nb++) {
                int d0 = bn + wc * 32 + nb * 8 + 2 * t4;
                float2 bi = *reinterpret_cast<const float2*>(btab + (size_t)qi * DM + d0);
                size_t off = ((size_t)b * NEXP + n) * DM + d0;
                float2 oa, ob;
                oa.x = rna(acca[c][nb][h * 2 + 0] * ia + bi.x);
                oa.y = rna(acca[c][nb][h * 2 + 1] * ia + bi.y);
                ob.x = rna(accb[c][nb][h * 2 + 0] * ib + bi.x);
                ob.y = rna(accb[c][nb][h * 2 + 1] * ib + bi.y);
                *reinterpret_cast<float2*>(CA + off) = oa;
                *reinterpret_cast<float2*>(CB + off) = ob;
            }
        }
    }
}

// ------------------------- backward class GEMM, tf32 dual (128x64 tile), blend+residual fused ----
// X1[b,l,d] = x + sel*(invA[b,l]*sum_n fa[l,n]*CA[b,n,d]) + (1-sel)*(...CB...)
__global__ void __launch_bounds__(256) classbw_tf32(
    const float* __restrict__ Z, const int* __restrict__ mask,
    const float* __restrict__ CA, const float* __restrict__ CB,
    const float* __restrict__ invA, const float* __restrict__ invB,
    const float* __restrict__ SELp, const float* __restrict__ X,
    float* __restrict__ X1)
{
    __shared__ float Aa[128 * ASTC], Ab[128 * ASTC];
    __shared__ float Ba[16 * BSTC], Bb[16 * BSTC];
    int tid = threadIdx.x;
    int b  = blockIdx.z;
    int bl = blockIdx.y * 128;   // l
    int bn = blockIdx.x * 64;    // d
    int warp = tid >> 5, lane = tid & 31;
    int wr = warp >> 1, wc = warp & 1;
    int g = lane >> 2, t4 = lane & 3;

    float acca[2][4][4] = {}, accb[2][4][4] = {};

    float4 za[2]; int4 ma[2]; float4 ca, cbv;
    int rb = tid >> 4, cb = (tid & 15) << 2;

    auto loadregs = [&](int k0) {
        #pragma unroll
        for (int h = 0; h < 2; h++) {
            int q = tid + h * 256;
            int rn = q >> 5, cl = (q & 31) << 2;
            size_t zoff = ((size_t)b * NEXP + k0 + rn) * LEN + bl + cl;
            za[h] = *reinterpret_cast<const float4*>(Z + zoff);
            ma[h] = *reinterpret_cast<const int4*>(mask + zoff);
        }
        size_t coff = ((size_t)b * NEXP + k0 + rb) * DM + bn + cb;
        ca  = *reinterpret_cast<const float4*>(CA + coff);
        cbv = *reinterpret_cast<const float4*>(CB + coff);
    };
    auto storeregs = [&]() {
        #pragma unroll
        for (int h = 0; h < 2; h++) {
            int q = tid + h * 256;
            int rn = q >> 5, cl = (q & 31) << 2;
            // transposed store: A[m=l][k=n]
            Aa[(cl + 0) * ASTC + rn] = ma[h].x ? rna(fmaxf(za[h].x, 0.f)) : 0.f;
            Ab[(cl + 0) * ASTC + rn] = ma[h].x ? rna(fmaxf(-za[h].x, 0.f)) : 0.f;
            Aa[(cl + 1) * ASTC + rn] = ma[h].y ? rna(fmaxf(za[h].y, 0.f)) : 0.f;
            Ab[(cl + 1) * ASTC + rn] = ma[h].y ? rna(fmaxf(-za[h].y, 0.f)) : 0.f;
            Aa[(cl + 2) * ASTC + rn] = ma[h].z ? rna(fmaxf(za[h].z, 0.f)) : 0.f;
            Ab[(cl + 2) * ASTC + rn] = ma[h].z ? rna(fmaxf(-za[h].z, 0.f)) : 0.f;
            Aa[(cl + 3) * ASTC + rn] = ma[h].w ? rna(fmaxf(za[h].w, 0.f)) : 0.f;
            Ab[(cl + 3) * ASTC + rn] = ma[h].w ? rna(fmaxf(-za[h].w, 0.f)) : 0.f;
        }
        *reinterpret_cast<float4*>(&Ba[rb * BSTC + cb]) = ca;
        *reinterpret_cast<float4*>(&Bb[rb * BSTC + cb]) = cbv;
    };
    auto compute = [&]() {
        #pragma unroll
        for (int kk = 0; kk < 16; kk += 8) {
            uint32_t afa[2][4], afb[2][4], bfa[4][2], bfb[4][2];
            #pragma unroll
            for (int c = 0; c < 2; c++) {
                const float* ap = &Aa[(wr * 32 + c * 16 + g) * ASTC + kk + t4];
                const float* bp = &Ab[(wr * 32 + c * 16 + g) * ASTC + kk + t4];
                afa[c][0] = __float_as_uint(ap[0]);
                afa[c][1] = __float_as_uint(ap[8 * ASTC]);
                afa[c][2] = __float_as_uint(ap[4]);
                afa[c][3] = __float_as_uint(ap[8 * ASTC + 4]);
                afb[c][0] = __float_as_uint(bp[0]);
                afb[c][1] = __float_as_uint(bp[8 * ASTC]);
                afb[c][2] = __float_as_uint(bp[4]);
                afb[c][3] = __float_as_uint(bp[8 * ASTC + 4]);
            }
            #pragma unroll
            for (int nb = 0; nb < 4; nb++) {
                const float* bpa = &Ba[(kk + t4) * BSTC + wc * 32 + nb * 8 + g];
                const float* bpb = &Bb[(kk + t4) * BSTC + wc * 32 + nb * 8 + g];
                bfa[nb][0] = __float_as_uint(bpa[0]);
                bfa[nb][1] = __float_as_uint(bpa[4 * BSTC]);
                bfb[nb][0] = __float_as_uint(bpb[0]);
                bfb[nb][1] = __float_as_uint(bpb[4 * BSTC]);
            }
            #pragma unroll
            for (int c = 0; c < 2; c++)
                #pragma unroll
                for (int nb = 0; nb < 4; nb++) {
                    mma8(acca[c][nb], afa[c], bfa[nb]);
                    mma8(accb[c][nb], afb[c], bfb[nb]);
                }
        }
    };

    loadregs(0);
    storeregs();
    __syncthreads();
    const int KT = NEXP / 16;    // 62
    for (int t = 0; t < KT; t++) {
        if (t + 1 < KT) loadregs((t + 1) * 16);
        compute();
        __syncthreads();
        if (t + 1 < KT) { storeregs(); __syncthreads(); }
    }

    #pragma unroll
    for (int c = 0; c < 2; c++) {
        #pragma unroll
        for (int h = 0; h < 2; h++) {
            int l = bl + wr * 32 + c * 16 + g + h * 8;
            float ia = invA[b * LEN + l];
            float ib = invB[b * LEN + l];
            #pragma unroll
            for (int nb = 0; nb < 4; nb++) {
                int d0 = bn + wc * 32 + nb * 8 + 2 * t4;
                size_t off = ((size_t)b * LEN + l) * DM + d0;
                float2 s2 = *reinterpret_cast<const float2*>(SELp + off);
                float2 x2 = *reinterpret_cast<const float2*>(X + off);
                float2 o;
                o.x = x2.x + s2.x * (acca[c][nb][h * 2 + 0] * ia)
                           + (1.f - s2.x) * (accb[c][nb][h * 2 + 0] * ib);
                o.y = x2.y + s2.y * (acca[c][nb][h * 2 + 1] * ia)
                           + (1.f - s2.y) * (accb[c][nb][h * 2 + 1] * ib);
                *reinterpret_cast<float2*>(X1 + off) = o;
            }
        }
    }
}

// ------------------------- launch -------------------------
extern "C" void kernel_launch(void* const* d_in, const int* in_sizes, int n_in,
                              void* d_out, int out_size)
{
    const float* x     = (const float*)d_in[0];
    const int*   nidx  = (const int*)d_in[1];
    const int*   mask  = (const int*)d_in[2];
    const float* ln1_g = (const float*)d_in[3];
    const float* ln1_b = (const float*)d_in[4];
    const float* ln2_g = (const float*)d_in[5];
    const float* ln2_b = (const float*)d_in[6];
    const float* q_tab = (const float*)d_in[7];
    const float* b_tab = (const float*)d_in[8];
    const float* Wk  = (const float*)d_in[9];  const float* bk   = (const float*)d_in[10];
    const float* Wa  = (const float*)d_in[11]; const float* ba   = (const float*)d_in[12];
    const float* Wa1 = (const float*)d_in[13]; const float* ba1  = (const float*)d_in[14];
    const float* Wb  = (const float*)d_in[15]; const float* bb   = (const float*)d_in[16];
    const float* Wb1 = (const float*)d_in[17]; const float* bb1  = (const float*)d_in[18];
    const float* Ws  = (const float*)d_in[19]; const float* bsel = (const float*)d_in[20];
    const float* Wf1 = (const float*)d_in[21]; const float* bf1  = (const float*)d_in[22];
    const float* Wf2 = (const float*)d_in[23]; const float* bf2  = (const float*)d_in[24];
    float* out = (float*)d_out;

    float *pX2, *pXK, *pEA0, *pEB0, *pAE, *pBE, *pSEL, *pX1, *pZ, *pCA, *pCB, *pH;
    float *pIAf, *pIBf, *pPA, *pPB, *pIAb, *pIBb, *pWR, *pQR;
    cudaGetSymbolAddress((void**)&pX2, g_X2);
    cudaGetSymbolAddress((void**)&pXK, g_XK);
    cudaGetSymbolAddress((void**)&pEA0, g_EA0);
    cudaGetSymbolAddress((void**)&pEB0, g_EB0);
    cudaGetSymbolAddress((void**)&pAE, g_AE);
    cudaGetSymbolAddress((void**)&pBE, g_BE);
    cudaGetSymbolAddress((void**)&pSEL, g_SEL);
    cudaGetSymbolAddress((void**)&pX1, g_X1);
    cudaGetSymbolAddress((void**)&pZ, g_Z);
    cudaGetSymbolAddress((void**)&pCA, g_CA);
    cudaGetSymbolAddress((void**)&pCB, g_CB);
    cudaGetSymbolAddress((void**)&pH, g_H);
    cudaGetSymbolAddress((void**)&pIAf, g_IAf);
    cudaGetSymbolAddress((void**)&pIBf, g_IBf);
    cudaGetSymbolAddress((void**)&pPA, g_PA);
    cudaGetSymbolAddress((void**)&pPB, g_PB);
    cudaGetSymbolAddress((void**)&pIAb, g_IAb);
    cudaGetSymbolAddress((void**)&pIBb, g_IBb);
    cudaGetSymbolAddress((void**)&pWR, g_WR);
    cudaGetSymbolAddress((void**)&pQR, g_QR);

    float* WkR  = pWR;
    float* WaR  = pWR + 262144;
    float* WbR  = pWR + 524288;
    float* WsR  = pWR + 786432;
    float* Wa1R = pWR + 1048576;
    float* Wb1R = pWR + 1310720;
    float* Wf1R = pWR + 1572864;
    float* Wf2R = pWR + 2621440;

    // 0. round weights + q_tab to tf32 (RNA)
    rnd_kernel<<<256, 256>>>(Wk,  WkR,  65536);
    rnd_kernel<<<256, 256>>>(Wa,  WaR,  65536);
    rnd_kernel<<<256, 256>>>(Wb,  WbR,  65536);
    rnd_kernel<<<256, 256>>>(Ws,  WsR,  65536);
    rnd_kernel<<<256, 256>>>(Wa1, Wa1R, 65536);
    rnd_kernel<<<256, 256>>>(Wb1, Wb1R, 65536);
    rnd_kernel<<<1024, 256>>>(Wf1, Wf1R, 262144);
    rnd_kernel<<<1024, 256>>>(Wf2, Wf2R, 262144);
    rnd_kernel<<<496, 256>>>(q_tab, pQR, 126976);

    // 1. LN1 (rounded output -> feeds tensor GEMMs)
    ln_kernel<true><<<M1, 128>>>(x, ln1_g, ln1_b, pX2);

    // 2. dense projections (tf32 tensor cores); AE/BE rounded for classfw
    dim3 gA(DM / GBN, M1 / GBM);
    gemm_tf32<0, true ><<<gA, 256>>>(pX2, WkR, bk, nullptr, pXK, M1, DM, DM);
    gemm_tf32<0, true ><<<gA, 256>>>(pX2, WaR, ba, nullptr, pEA0, M1, DM, DM);
    gemm_tf32<0, true ><<<gA, 256>>>(pX2, WbR, bb, nullptr, pEB0, M1, DM, DM);
    gemm_tf32<1, false><<<gA, 256>>>(pX2, WsR, bsel, nullptr, pSEL, M1, DM, DM);
    gemm_tf32<3, true ><<<gA, 256>>>(pEA0, Wa1R, ba1, pEA0, pAE, M1, DM, DM);
    gemm_tf32<3, true ><<<gA, 256>>>(pEB0, Wb1R, bb1, pEB0, pBE, M1, DM, DM);

    // 3. z = Q_exp @ XK^T / sqrt(d)   (tf32 tensor cores)
    zgemm_tf32<<<dim3(LEN / GBN, (NEXP + GBM - 1) / GBM, BSZ), 256>>>(nidx, pQR, pXK, pZ);

    // 4. normalization sums
    fw_sums<<<(BSZ * NEXP) / 8, 256>>>(pZ, mask, pIAf, pIBf);
    bw_partial<<<dim3(BSZ, NSPLIT), LEN>>>(pZ, mask, pPA, pPB);
    bw_final<<<BSZ, LEN>>>(pPA, pPB, pIAb, pIBb);

    // 5. forward classes (tf32 dual), 6. backward classes + blend + residual (tf32 dual)
    classfw_tf32<<<dim3(DM / 64, (NEXP + 127) / 128, BSZ), 256>>>(pZ, mask, pAE, pBE, pIAf, pIBf,
                                                                  nidx, b_tab, pCA, pCB);
    classbw_tf32<<<dim3(DM / 64, LEN / 128, BSZ), 256>>>(pZ, mask, pCA, pCB, pIAb, pIBb,
                                                         pSEL, x, pX1);

    // 7. LN2 + FFN (tf32 tensor cores; residual fused into final store)
    ln_kernel<true><<<M1, 128>>>(pX1, ln2_g, ln2_b, pX2);
    gemm_tf32<2, true ><<<dim3(DFF / GBN, M1 / GBM), 256>>>(pX2, Wf1R, bf1, nullptr, pH, M1, DFF, DM);
    gemm_tf32<4, false><<<dim3(DM / GBN, M1 / GBM), 256>>>(pH, Wf2R, bf2, pX1, out, M1, DM, DFF);
}